// round 9
// baseline (speedup 1.0000x reference)
#include <cuda_runtime.h>
#include <cuda_bf16.h>

// Scratch (allocation-free rule: __device__ globals; zero-initialized)
__device__ float g_SC[1024];       // S_C[k*4+l]
__device__ float g_SX[128 * 64];   // S_x[b*64 + h1*8 + w2]
__device__ int   g_cnt[128];       // producers done per b (target 8)
__device__ int   g_cnt2[128];      // consumers passed per b (target 8) -> self-reset
__device__ int   g_cntC;           // sumC blocks done (target 128)
__device__ int   g_cntC2;          // SC consumers passed (target 1024) -> self-reset

// ---------------------------------------------------------------------------
// Single persistent-wave kernel: 1152 blocks x 192 threads, ALL resident
// (launch_bounds(192,8): 8 blk/SM x 192 = 1536 thr, regs<=40, smem 3KB).
//   blocks [0,128):    sumC -> g_SC, publish g_cntC.
//   blocks [128,1152): producer+consumer for (b = i/8, h1 = i%8):
//     produce: S_x[b][h1][0..8) from 32 rows (r = h1+8q), bin-safe smem tree
//              (strides that are multiples of 24 floats preserve w2).
//     publish: threadfence + atomicAdd(g_cnt[b]).
//     consume: t0 spins until cnt[b]==8 && cntC==128, recycles counters
//              (last consumer zeroes cnt/cnt2 -> no init kernel needed),
//              then block expands out[b, h1*128 .. h1*128+128, :].
//   Expand stores from early finishers overlap stragglers' DRAM reads.
// ---------------------------------------------------------------------------
__global__ void __launch_bounds__(192, 8)
main_kernel(const float* __restrict__ x,
            const float* __restrict__ C,
            float* __restrict__ out) {
    __shared__ float sm[768];
    const int t = threadIdx.x;             // 0..191

    if (blockIdx.x < 128) {
        // ---------------- sumC ----------------
        float4* sm4 = (float4*)sm;         // [c(2)][rg(96)]
        const int cid = blockIdx.x;
        const int c  = t & 1;
        const int rg = t >> 1;             // 0..95
        const int c4 = 2 * cid + c;
        const float4* __restrict__ C4 = (const float4*)C;   // 256 f4/row
        float4 acc = make_float4(0.f, 0.f, 0.f, 0.f);
#pragma unroll 8
        for (int q = 0; q < 32; ++q) {
            float4 v = C4[(rg + 96 * q) * 256 + c4];
            acc.x += v.x; acc.y += v.y; acc.z += v.z; acc.w += v.w;
        }
        sm4[c * 96 + rg] = acc;
        __syncthreads();
        for (int s = 48; s >= 3; s >>= 1) {
            if (rg < s) {
                float4 a  = sm4[c * 96 + rg];
                float4 bv = sm4[c * 96 + rg + s];
                a.x += bv.x; a.y += bv.y; a.z += bv.z; a.w += bv.w;
                sm4[c * 96 + rg] = a;
            }
            __syncthreads();
        }
        if (rg == 0) {
            float4 a0 = sm4[c * 96 + 0];
            float4 a1 = sm4[c * 96 + 1];
            float4 a2 = sm4[c * 96 + 2];
            float4 r;
            r.x = a0.x + a1.x + a2.x;
            r.y = a0.y + a1.y + a2.y;
            r.z = a0.z + a1.z + a2.z;
            r.w = a0.w + a1.w + a2.w;
            ((float4*)g_SC)[2 * cid + c] = r;
        }
        __threadfence();
        __syncthreads();
        if (t == 0) atomicAdd(&g_cntC, 1);
        return;
    }

    // ---------------- producer: (b, h1), one full bin-row ----------------
    const int idx = blockIdx.x - 128;      // 0..1023
    const int b   = idx >> 3;
    const int h1  = idx & 7;

    const float4* __restrict__ x4 = (const float4*)x;   // 192 f4 per row
    const long base = (long)b * 49152 + (long)h1 * 192 + t;

    float4 acc = make_float4(0.f, 0.f, 0.f, 0.f);
#pragma unroll 8
    for (int q = 0; q < 32; ++q) {
        float4 v = x4[base + (long)q * 1536];            // +8 rows per step
        acc.x += v.x; acc.y += v.y; acc.z += v.z; acc.w += v.w;
    }
    sm[4 * t + 0] = acc.x;
    sm[4 * t + 1] = acc.y;
    sm[4 * t + 2] = acc.z;
    sm[4 * t + 3] = acc.w;
    __syncthreads();

    // bin-safe tree: strides 384/192/96/48/24 (all multiples of 24 floats)
    sm[t]       += sm[t + 384];
    sm[t + 192] += sm[t + 576];
    __syncthreads();
    sm[t] += sm[t + 192];
    __syncthreads();
    if (t < 96) sm[t] += sm[t + 96];
    __syncthreads();
    if (t < 48) sm[t] += sm[t + 48];
    __syncthreads();
    if (t < 24) sm[t] += sm[t + 24];
    __syncthreads();
    if (t < 8)
        g_SX[b * 64 + h1 * 8 + t] = sm[3 * t] + sm[3 * t + 1] + sm[3 * t + 2];
    __threadfence();
    __syncthreads();
    if (t == 0) atomicAdd(&g_cnt[b], 1);

    // ---------------- consume: wait for b's 8 bins + S_C ----------------
    if (t == 0) {
        while (atomicAdd(&g_cnt[b], 0) < 8)  __nanosleep(64);
        while (atomicAdd(&g_cntC, 0) < 128)  __nanosleep(64);
        __threadfence();
        // recycle counters (no init kernel): last consumer resets to zero.
        int c2 = atomicAdd(&g_cntC2, 1);
        if (c2 == 1023) { atomicExch(&g_cntC, 0); atomicExch(&g_cntC2, 0); }
        int v2 = atomicAdd(&g_cnt2[b], 1);
        if (v2 == 7)    { atomicExch(&g_cnt[b], 0); atomicExch(&g_cnt2[b], 0); }
    }
    __syncthreads();

    // Stage scales: sc (128 floats for kl in [h1*128, h1*128+128)) + sx (64)
    if (t < 128)       sm[t] = g_SC[h1 * 128 + t];
    else if (t < 144)  ((float4*)(sm + 128))[t - 128] =
                           ((const float4*)g_SX)[b * 16 + (t - 128)];
    __syncthreads();

    // Expand this slice: 2048 float4, coalesced
    const float4* sx4 = (const float4*)(sm + 128);
    float4* out4 = (float4*)out + (long)b * 16384 + h1 * 2048;
    for (int j = t; j < 2048; j += 192) {
        const float  sc = sm[j >> 4];      // kl_local = j/16
        const float4 sx = sx4[j & 15];
        float4 r;
        r.x = sc * sx.x; r.y = sc * sx.y; r.z = sc * sx.z; r.w = sc * sx.w;
        out4[j] = r;
    }
}

// ---------------------------------------------------------------------------
extern "C" void kernel_launch(void* const* d_in, const int* in_sizes, int n_in,
                              void* d_out, int out_size) {
    const float* x = (const float*)d_in[0];  // [128,256,256,3]
    const float* C = (const float*)d_in[1];  // [768,4,256,4]
    float* out = (float*)d_out;              // [128,256,4,8,8]

    main_kernel<<<1152, 192>>>(x, C, out);
}